// round 5
// baseline (speedup 1.0000x reference)
#include <cuda_runtime.h>
#include <cuda_bf16.h>

#define IW 1280
#define IH 720
#define IB 32

#define PADL 66                 // pair entries for x0 in [-66, -1]
#define ROWP (PADL + IW)        // 1346 float2 entries = 10.8 KB

__global__ __launch_bounds__(320) void warp_disp_hrow(
    const float* __restrict__ img,
    const float* __restrict__ disp,
    float* __restrict__ out)
{
    __shared__ float2 s2[ROWP];

    const int blk = blockIdx.x;     // = b*IH + y
    const int y   = blk % IH;
    const int b   = blk / IH;
    const int t   = threadIdx.x;    // 320 threads; thread t -> pixels 4t..4t+3
    const int xb  = t * 4;

    // ---- vertical terms (uniform per row): iy = y*H/(H-1) - 0.5 ----
    float iy  = fmaf((float)y, (float)IH / (float)(IH - 1), -0.5f);
    float y0f = floorf(iy);
    float wy1 = iy - y0f;
    float wy0 = 1.0f - wy1;
    int   y0  = (int)y0f;
    int   y1  = y0 + 1;
    bool  vy0 = (unsigned)y0 < (unsigned)IH;
    bool  vy1 = (unsigned)y1 < (unsigned)IH;

    const float* imgb = img + (size_t)b * (IH * IW);
    const float* r0p  = imgb + (vy0 ? y0 : 0) * IW;
    const float* r1p  = imgb + (vy1 ? y1 : 0) * IW;

    // prefetch disp early (overlaps row-load latency)
    const int p = blk * IW + xb;
    float4 d4 = *reinterpret_cast<const float4*>(disp + p);

    // ---- load both source rows (registers only), vertical lerp ----
    float4 z4 = make_float4(0.f, 0.f, 0.f, 0.f);
    float4 a0 = vy0 ? reinterpret_cast<const float4*>(r0p)[t] : z4;
    float4 a1 = vy1 ? reinterpret_cast<const float4*>(r1p)[t] : z4;
    float  e0 = 0.f, e1 = 0.f;       // boundary element x = 4t+4
    if (t < 319) {
        e0 = vy0 ? __ldg(r0p + xb + 4) : 0.f;
        e1 = vy1 ? __ldg(r1p + xb + 4) : 0.f;
    }

    float h0 = fmaf(wy0, a0.x, wy1 * a1.x);
    float h1 = fmaf(wy0, a0.y, wy1 * a1.y);
    float h2 = fmaf(wy0, a0.z, wy1 * a1.z);
    float h3 = fmaf(wy0, a0.w, wy1 * a1.w);
    float h4 = fmaf(wy0, e0,   wy1 * e1);

    // ---- write pair-duplicated h row: s[x] = (h[x], h[x+1]) ----
    float2* sp = s2 + PADL;
    sp[xb + 0] = make_float2(h0, h1);
    sp[xb + 1] = make_float2(h1, h2);
    sp[xb + 2] = make_float2(h2, h3);
    sp[xb + 3] = make_float2(h3, h4);
    if (t < PADL - 1)            // zero pairs for x0 in [-66, -2]
        sp[-PADL + t] = make_float2(0.f, 0.f);
    if (t == 0)                  // x0 = -1: left tap OOB (0), right tap = h[0]
        sp[-1] = make_float2(0.f, h0);
    __syncthreads();

    // ---- per pixel: one LDS.64 + horizontal lerp ----
    const float Ax = (float)IW / (float)(IW - 1);
    float dv[4] = {d4.x, d4.y, d4.z, d4.w};
    float res[4];

#pragma unroll
    for (int i = 0; i < 4; i++) {
        float u   = (float)(xb + i) - dv[i];
        float ix  = fmaf(u, Ax, -0.5f);
        float x0f = floorf(ix);
        float wx1 = ix - x0f;
        float wx0 = 1.0f - wx1;
        int   x0  = (int)x0f;         // in [-65, 1279]

        float2 pr = sp[x0];
        res[i] = fmaf(pr.y, wx1, pr.x * wx0);
    }

    *reinterpret_cast<float4*>(out + p) = make_float4(res[0], res[1], res[2], res[3]);
}

extern "C" void kernel_launch(void* const* d_in, const int* in_sizes, int n_in,
                              void* d_out, int out_size)
{
    const float* right_img = (const float*)d_in[0];
    const float* disp      = (const float*)d_in[1];
    float*       out       = (float*)d_out;

    const int blocks = IB * IH;       // 23040 CTAs, one per output row
    warp_disp_hrow<<<blocks, 320>>>(right_img, disp, out);
}

// round 6
// speedup vs baseline: 1.6149x; 1.6149x over previous
#include <cuda_runtime.h>
#include <cuda_bf16.h>

#define IW 1280
#define IH 720
#define IB 32

#define PADL 68                 // zero floats for x0 in [-66, -1] (+2 align slack)
#define ROWF (PADL + IW + 4)    // 1352 floats = 5.4 KB

__global__ __launch_bounds__(320) void warp_disp_h1(
    const float* __restrict__ img,
    const float* __restrict__ disp,
    float* __restrict__ out)
{
    __shared__ float sm[ROWF];

    const int blk = blockIdx.x;     // = b*IH + y
    const int y   = blk % IH;
    const int b   = blk / IH;
    const int t   = threadIdx.x;    // 320 threads; thread t -> pixels 4t..4t+3
    const int xb  = t * 4;

    // ---- vertical terms (uniform per row): iy = y*H/(H-1) - 0.5 ----
    float iy  = fmaf((float)y, (float)IH / (float)(IH - 1), -0.5f);
    float y0f = floorf(iy);
    float wy1 = iy - y0f;
    float wy0 = 1.0f - wy1;
    int   y0  = (int)y0f;
    int   y1  = y0 + 1;
    bool  vy0 = (unsigned)y0 < (unsigned)IH;
    bool  vy1 = (unsigned)y1 < (unsigned)IH;

    const float* imgb = img + (size_t)b * (IH * IW);
    const float* r0p  = imgb + (vy0 ? y0 : 0) * IW;
    const float* r1p  = imgb + (vy1 ? y1 : 0) * IW;

    // disp prefetch (consumed only after the barrier — overlaps row loads)
    const int p = blk * IW + xb;
    float4 d4 = *reinterpret_cast<const float4*>(disp + p);

    // ---- load both source rows (registers), vertical lerp, one STS.128 ----
    float4 z4 = make_float4(0.f, 0.f, 0.f, 0.f);
    float4 a0 = vy0 ? reinterpret_cast<const float4*>(r0p)[t] : z4;
    float4 a1 = vy1 ? reinterpret_cast<const float4*>(r1p)[t] : z4;

    float4 h;
    h.x = fmaf(wy0, a0.x, wy1 * a1.x);
    h.y = fmaf(wy0, a0.y, wy1 * a1.y);
    h.z = fmaf(wy0, a0.z, wy1 * a1.z);
    h.w = fmaf(wy0, a0.w, wy1 * a1.w);

    float* sp = sm + PADL;
    *reinterpret_cast<float4*>(sp + xb) = h;
    if (t < PADL / 4)                       // left zero pad: floats [-68, -1]
        *reinterpret_cast<float4*>(sm + t * 4) = z4;
    if (t == 319)                           // right pad: h[1280] = 0 (x1 OOB)
        *reinterpret_cast<float4*>(sp + IW) = z4;
    __syncthreads();

    // ---- per pixel: 2 scalar LDS + horizontal lerp ----
    const float Ax = (float)IW / (float)(IW - 1);
    float dv[4] = {d4.x, d4.y, d4.z, d4.w};
    float res[4];

#pragma unroll
    for (int i = 0; i < 4; i++) {
        float u   = (float)(xb + i) - dv[i];
        float ix  = fmaf(u, Ax, -0.5f);
        float x0f = floorf(ix);
        float wx1 = ix - x0f;
        float wx0 = 1.0f - wx1;
        int   x0  = (int)x0f;               // in [-65, 1279]

        float v0 = sp[x0];
        float v1 = sp[x0 + 1];
        res[i] = fmaf(v1, wx1, v0 * wx0);
    }

    *reinterpret_cast<float4*>(out + p) = make_float4(res[0], res[1], res[2], res[3]);
}

extern "C" void kernel_launch(void* const* d_in, const int* in_sizes, int n_in,
                              void* d_out, int out_size)
{
    const float* right_img = (const float*)d_in[0];
    const float* disp      = (const float*)d_in[1];
    float*       out       = (float*)d_out;

    const int blocks = IB * IH;             // 23040 CTAs, one per output row
    warp_disp_h1<<<blocks, 320>>>(right_img, disp, out);
}